// round 1
// baseline (speedup 1.0000x reference)
#include <cuda_runtime.h>
#include <cuda_bf16.h>

#define N_NODES   10000
#define N_EDGES   640000
#define FEATS     128
#define F4        (FEATS/4)   // 32 float4 per row

// ---------------- scratch (no allocation allowed) ----------------
__device__ int    g_off[N_NODES + 1];     // CSR offsets (exclusive)
__device__ int    g_cur[N_NODES];         // scatter cursors
__device__ int    g_srcs[N_EDGES];        // src node per edge, grouped by dst
__device__ float4 g_h[N_NODES * F4];      // h = x + agg
__device__ int    g_idx64;                // 1 if indices are int64, else int32

// ---------------- index dtype handling ----------------
__device__ __forceinline__ int load_idx(const void* p, int e, int is64) {
    if (is64) return (int)((const long long*)p)[e];
    return ((const int*)p)[e];
}

__global__ void k_detect(const void* src) {
    if (threadIdx.x == 0 && blockIdx.x == 0) {
        const long long* p = (const long long*)src;
        int ok = 1;
        #pragma unroll 1
        for (int i = 0; i < 64; i++) {
            long long v = p[i];
            if (v < 0 || v >= N_NODES) { ok = 0; break; }
        }
        g_idx64 = ok;
    }
}

// ---------------- CSR build ----------------
__global__ void k_zero() {
    int i = blockIdx.x * blockDim.x + threadIdx.x;
    if (i <= N_NODES) g_off[i] = 0;
}

__global__ void k_hist(const void* dst) {
    int e = blockIdx.x * blockDim.x + threadIdx.x;
    if (e >= N_EDGES) return;
    int is64 = g_idx64;
    int d = load_idx(dst, e, is64);
    atomicAdd(&g_off[d + 1], 1);
}

// single-block inclusive scan over g_off[0..N_NODES]; also primes g_cur
__global__ void k_scan() {
    __shared__ int sh[1024];
    __shared__ int s_carry;
    int tid = threadIdx.x;
    if (tid == 0) s_carry = 0;
    __syncthreads();
    for (int base = 0; base <= N_NODES; base += 1024) {
        int i = base + tid;
        int v = (i <= N_NODES) ? g_off[i] : 0;
        sh[tid] = v;
        __syncthreads();
        for (int d = 1; d < 1024; d <<= 1) {
            int t = (tid >= d) ? sh[tid - d] : 0;
            __syncthreads();
            sh[tid] += t;
            __syncthreads();
        }
        int inc = sh[tid] + s_carry;
        int tile_total = sh[1023];
        if (i <= N_NODES) {
            g_off[i] = inc;
            if (i < N_NODES) g_cur[i] = inc;
        }
        __syncthreads();
        if (tid == 0) s_carry += tile_total;
        __syncthreads();
    }
}

__global__ void k_scatter(const void* src, const void* dst) {
    int e = blockIdx.x * blockDim.x + threadIdx.x;
    if (e >= N_EDGES) return;
    int is64 = g_idx64;
    int d = load_idx(dst, e, is64);
    int s = load_idx(src, e, is64);
    int pos = atomicAdd(&g_cur[d], 1);
    g_srcs[pos] = s;
}

// ---------------- aggregation: one warp per node ----------------
__global__ void k_agg(const float4* __restrict__ x4) {
    int gtid = blockIdx.x * blockDim.x + threadIdx.x;
    int node = gtid >> 5;
    int lane = gtid & 31;
    if (node >= N_NODES) return;

    float4 acc = x4[node * F4 + lane];   // self term (1+eps)*x, eps=0
    int e   = g_off[node];
    int end = g_off[node + 1];

    for (; e + 4 <= end; e += 4) {
        int s0 = g_srcs[e], s1 = g_srcs[e + 1], s2 = g_srcs[e + 2], s3 = g_srcs[e + 3];
        float4 a = x4[s0 * F4 + lane];
        float4 b = x4[s1 * F4 + lane];
        float4 c = x4[s2 * F4 + lane];
        float4 d = x4[s3 * F4 + lane];
        acc.x += (a.x + b.x) + (c.x + d.x);
        acc.y += (a.y + b.y) + (c.y + d.y);
        acc.z += (a.z + b.z) + (c.z + d.z);
        acc.w += (a.w + b.w) + (c.w + d.w);
    }
    for (; e < end; e++) {
        float4 a = x4[g_srcs[e] * F4 + lane];
        acc.x += a.x; acc.y += a.y; acc.z += a.z; acc.w += a.w;
    }
    g_h[node * F4 + lane] = acc;
}

// ---------------- GEMM: out = h @ W^T + b ----------------
// block: 32 rows x 128 cols, 256 threads, 4x4 register tile per thread
#define SW_STRIDE 36   // padded smem row stride (floats), 16B-aligned, spreads banks
__global__ void k_gemm(const float* __restrict__ W,
                       const float* __restrict__ bias,
                       float* __restrict__ out) {
    __shared__ float shW[128 * SW_STRIDE];  // W rows 0..127, k-chunk of 32
    __shared__ float shH[32 * SW_STRIDE];   // h rows, k-chunk of 32

    int tid  = threadIdx.x;
    int lane = tid & 31;
    int wrp  = tid >> 5;          // 0..7 -> row group
    int row0 = blockIdx.x * 32;

    float acc[4][4];
    #pragma unroll
    for (int i = 0; i < 4; i++)
        #pragma unroll
        for (int j = 0; j < 4; j++) acc[i][j] = 0.f;

    const float* hflat = (const float*)g_h;

    for (int kk = 0; kk < FEATS; kk += 32) {
        // load W chunk: 128 rows x 32 cols = 1024 float4 / 256 thr = 4 each
        #pragma unroll
        for (int i = 0; i < 4; i++) {
            int t  = tid + i * 256;
            int r  = t >> 3;
            int c4 = (t & 7) * 4;
            float4 v = *(const float4*)&W[r * FEATS + kk + c4];
            *(float4*)&shW[r * SW_STRIDE + c4] = v;
        }
        // load H chunk: 32 rows x 32 cols = 256 float4, 1 each
        {
            int r  = tid >> 3;
            int c4 = (tid & 7) * 4;
            int gr = row0 + r;
            float4 v = (gr < N_NODES)
                       ? *(const float4*)&hflat[gr * FEATS + kk + c4]
                       : make_float4(0.f, 0.f, 0.f, 0.f);
            *(float4*)&shH[r * SW_STRIDE + c4] = v;
        }
        __syncthreads();

        #pragma unroll
        for (int k4 = 0; k4 < 32; k4 += 4) {
            float4 ha[4], wb[4];
            #pragma unroll
            for (int ri = 0; ri < 4; ri++)
                ha[ri] = *(const float4*)&shH[(wrp * 4 + ri) * SW_STRIDE + k4];
            #pragma unroll
            for (int ci = 0; ci < 4; ci++)
                wb[ci] = *(const float4*)&shW[(lane + 32 * ci) * SW_STRIDE + k4];
            #pragma unroll
            for (int ri = 0; ri < 4; ri++)
                #pragma unroll
                for (int ci = 0; ci < 4; ci++) {
                    acc[ri][ci] += ha[ri].x * wb[ci].x;
                    acc[ri][ci] += ha[ri].y * wb[ci].y;
                    acc[ri][ci] += ha[ri].z * wb[ci].z;
                    acc[ri][ci] += ha[ri].w * wb[ci].w;
                }
        }
        __syncthreads();
    }

    #pragma unroll
    for (int ri = 0; ri < 4; ri++) {
        int r = row0 + wrp * 4 + ri;
        if (r >= N_NODES) continue;
        #pragma unroll
        for (int ci = 0; ci < 4; ci++) {
            int c = lane + 32 * ci;
            out[r * FEATS + c] = acc[ri][ci] + bias[c];
        }
    }
}

// ---------------- launch ----------------
extern "C" void kernel_launch(void* const* d_in, const int* in_sizes, int n_in,
                              void* d_out, int out_size) {
    const float* x    = (const float*)d_in[0];
    const void*  src  = d_in[1];
    const void*  dst  = d_in[2];
    const float* W    = (const float*)d_in[3];
    const float* bias = (const float*)d_in[4];
    float* out = (float*)d_out;

    k_detect<<<1, 32>>>(src);
    k_zero<<<(N_NODES + 1 + 255) / 256, 256>>>();
    k_hist<<<(N_EDGES + 255) / 256, 256>>>(dst);
    k_scan<<<1, 1024>>>();
    k_scatter<<<(N_EDGES + 255) / 256, 256>>>(src, dst);
    k_agg<<<(N_NODES * 32 + 255) / 256, 256>>>((const float4*)x);
    k_gemm<<<(N_NODES + 31) / 32, 256>>>(W, bias, out);
}

// round 2
// speedup vs baseline: 1.0590x; 1.0590x over previous
#include <cuda_runtime.h>
#include <cuda_bf16.h>

#define N_NODES   10000
#define N_EDGES   640000
#define FEATS     128
#define F4        (FEATS/4)   // 32 float4 per row

// ---------------- scratch (no allocation allowed) ----------------
__device__ int    g_off[N_NODES + 1];     // CSR offsets (exclusive)
__device__ int    g_cur[N_NODES];         // scatter cursors
__device__ int    g_srcs[N_EDGES];        // src node per edge, grouped by dst
__device__ int    g_idx64;                // 1 if indices are int64, else int32

// ---------------- index dtype handling ----------------
__device__ __forceinline__ int load_idx(const void* p, int e, int is64) {
    if (is64) return (int)((const long long*)p)[e];
    return ((const int*)p)[e];
}

// fused: zero g_off everywhere; block 0 / warp 0 detects index dtype in parallel
__global__ void k_init(const void* src) {
    int i = blockIdx.x * blockDim.x + threadIdx.x;
    if (i <= N_NODES) g_off[i] = 0;
    if (blockIdx.x == 0 && threadIdx.x < 32) {
        const long long* p = (const long long*)src;
        // each lane checks 2 of the first 64 values interpreted as int64
        long long v0 = p[threadIdx.x * 2];
        long long v1 = p[threadIdx.x * 2 + 1];
        int bad = (v0 < 0 || v0 >= N_NODES || v1 < 0 || v1 >= N_NODES);
        unsigned m = __ballot_sync(0xFFFFFFFFu, bad);
        if (threadIdx.x == 0) g_idx64 = (m == 0u);
    }
}

__global__ void k_hist(const void* dst) {
    int e = blockIdx.x * blockDim.x + threadIdx.x;
    if (e >= N_EDGES) return;
    int is64 = g_idx64;
    int d = load_idx(dst, e, is64);
    atomicAdd(&g_off[d + 1], 1);
}

// single-block scan: 1024 threads x 10-element sequential chunks + shfl scan
__global__ void k_scan() {
    const int CH = 10;   // 1024 * 10 = 10240 >= 10001
    int tid  = threadIdx.x;
    int lane = tid & 31;
    int wrp  = tid >> 5;
    int base = tid * CH;

    int v[CH];
    int s = 0;
    #pragma unroll
    for (int j = 0; j < CH; j++) {
        int i = base + j;
        int a = (i <= N_NODES) ? g_off[i] : 0;
        s += a;
        v[j] = s;                  // local inclusive
    }

    // warp inclusive scan of thread totals
    int ss = s;
    #pragma unroll
    for (int d = 1; d < 32; d <<= 1) {
        int t = __shfl_up_sync(0xFFFFFFFFu, ss, d);
        if (lane >= d) ss += t;
    }
    __shared__ int wt[32];
    if (lane == 31) wt[wrp] = ss;
    __syncthreads();
    if (wrp == 0) {
        int x = wt[lane];
        #pragma unroll
        for (int d = 1; d < 32; d <<= 1) {
            int t = __shfl_up_sync(0xFFFFFFFFu, x, d);
            if (lane >= d) x += t;
        }
        wt[lane] = x;
    }
    __syncthreads();

    int excl = ss - s + (wrp ? wt[wrp - 1] : 0);  // exclusive prefix for this thread
    #pragma unroll
    for (int j = 0; j < CH; j++) {
        int i = base + j;
        if (i <= N_NODES) {
            int val = excl + v[j];
            g_off[i] = val;
            if (i < N_NODES) g_cur[i] = val;
        }
    }
}

__global__ void k_scatter(const void* src, const void* dst) {
    int e = blockIdx.x * blockDim.x + threadIdx.x;
    if (e >= N_EDGES) return;
    int is64 = g_idx64;
    int d = load_idx(dst, e, is64);
    int s = load_idx(src, e, is64);
    int pos = atomicAdd(&g_cur[d], 1);
    g_srcs[pos] = s;
}

// ---------------- fused aggregation + GEMM ----------------
// Block = 256 threads (8 warps), 32 nodes per block.
// Phase A: each warp aggregates 4 nodes (warp-per-node, lane holds one float4)
//          and writes h = x + sum_neighbors(x) into smem.
// Phase B: register-tiled GEMM out = h @ W^T + b (h from smem, W staged per chunk).
#define SW_STRIDE 36    // shW row stride (floats)
#define SH_STRIDE 136   // shH row stride (floats, mult of 4 for float4 stores)
__global__ void k_agg_gemm(const float4* __restrict__ x4,
                           const float*  __restrict__ W,
                           const float*  __restrict__ bias,
                           float* __restrict__ out) {
    __shared__ float shW[128 * SW_STRIDE];  // 18.4 KB
    __shared__ float shH[32 * SH_STRIDE];   // 17.4 KB

    int tid  = threadIdx.x;
    int lane = tid & 31;
    int wrp  = tid >> 5;            // 0..7
    int row0 = blockIdx.x * 32;

    // ---- Phase A: aggregate 4 nodes per warp ----
    #pragma unroll 1
    for (int r = 0; r < 4; r++) {
        int node = row0 + wrp * 4 + r;
        if (node >= N_NODES) break;
        float4 acc = x4[node * F4 + lane];   // self term, eps=0
        int e   = g_off[node];
        int end = g_off[node + 1];
        for (; e + 4 <= end; e += 4) {
            int s0 = g_srcs[e], s1 = g_srcs[e + 1], s2 = g_srcs[e + 2], s3 = g_srcs[e + 3];
            float4 a = x4[s0 * F4 + lane];
            float4 b = x4[s1 * F4 + lane];
            float4 c = x4[s2 * F4 + lane];
            float4 d = x4[s3 * F4 + lane];
            acc.x += (a.x + b.x) + (c.x + d.x);
            acc.y += (a.y + b.y) + (c.y + d.y);
            acc.z += (a.z + b.z) + (c.z + d.z);
            acc.w += (a.w + b.w) + (c.w + d.w);
        }
        for (; e < end; e++) {
            float4 a = x4[g_srcs[e] * F4 + lane];
            acc.x += a.x; acc.y += a.y; acc.z += a.z; acc.w += a.w;
        }
        *(float4*)&shH[(wrp * 4 + r) * SH_STRIDE + lane * 4] = acc;
    }
    __syncthreads();

    // ---- Phase B: GEMM 32x128 @ 128x128^T ----
    float acc[4][4];
    #pragma unroll
    for (int i = 0; i < 4; i++)
        #pragma unroll
        for (int j = 0; j < 4; j++) acc[i][j] = 0.f;

    for (int kk = 0; kk < FEATS; kk += 32) {
        // stage W chunk: 128 rows x 32 cols = 1024 float4 / 256 thr = 4 each
        #pragma unroll
        for (int i = 0; i < 4; i++) {
            int t  = tid + i * 256;
            int r  = t >> 3;
            int c4 = (t & 7) * 4;
            float4 v = *(const float4*)&W[r * FEATS + kk + c4];
            *(float4*)&shW[r * SW_STRIDE + c4] = v;
        }
        __syncthreads();

        #pragma unroll
        for (int k4 = 0; k4 < 32; k4 += 4) {
            float4 ha[4], wb[4];
            #pragma unroll
            for (int ri = 0; ri < 4; ri++)   // warp-uniform address: broadcast
                ha[ri] = *(const float4*)&shH[(wrp * 4 + ri) * SH_STRIDE + kk + k4];
            #pragma unroll
            for (int ci = 0; ci < 4; ci++)
                wb[ci] = *(const float4*)&shW[(lane + 32 * ci) * SW_STRIDE + k4];
            #pragma unroll
            for (int ri = 0; ri < 4; ri++)
                #pragma unroll
                for (int ci = 0; ci < 4; ci++) {
                    acc[ri][ci] += ha[ri].x * wb[ci].x;
                    acc[ri][ci] += ha[ri].y * wb[ci].y;
                    acc[ri][ci] += ha[ri].z * wb[ci].z;
                    acc[ri][ci] += ha[ri].w * wb[ci].w;
                }
        }
        __syncthreads();
    }

    #pragma unroll
    for (int ri = 0; ri < 4; ri++) {
        int r = row0 + wrp * 4 + ri;
        if (r >= N_NODES) continue;
        #pragma unroll
        for (int ci = 0; ci < 4; ci++) {
            int c = lane + 32 * ci;
            out[r * FEATS + c] = acc[ri][ci] + bias[c];
        }
    }
}

// ---------------- launch ----------------
extern "C" void kernel_launch(void* const* d_in, const int* in_sizes, int n_in,
                              void* d_out, int out_size) {
    const float* x    = (const float*)d_in[0];
    const void*  src  = d_in[1];
    const void*  dst  = d_in[2];
    const float* W    = (const float*)d_in[3];
    const float* bias = (const float*)d_in[4];
    float* out = (float*)d_out;

    k_init<<<(N_NODES + 1 + 255) / 256, 256>>>(src);
    k_hist<<<(N_EDGES + 255) / 256, 256>>>(dst);
    k_scan<<<1, 1024>>>();
    k_scatter<<<(N_EDGES + 255) / 256, 256>>>(src, dst);
    k_agg_gemm<<<(N_NODES + 31) / 32, 256>>>((const float4*)x, W, bias, out);
}